// round 9
// baseline (speedup 1.0000x reference)
#include <cuda_runtime.h>
#include <math.h>

// Problem constants
#define SS 3       // REFINE_LAYERS
#define BB 32      // batch
#define NN 2000    // priors
#define LL 4       // max lanes
#define DD 78      // 2 + 4 + 72
#define NP 72      // num points offsets
#define PRI 96     // priors per k_cost block
#define CTHR 96    // threads per k_cost block (3 warps)
#define NCHK 21    // ceil(2000/96); last chunk has 80 valid
#define NSLICE (2 * SS * BB)   // 192
#define CLSG 8     // sb-groups for cls partials
#define SBPG (SS * BB / CLSG)  // 12 sb per group
#define NBLK2 56   // blocks in kernel 2 (32 cls + 24 matched)

// Scratch (device globals; no allocation allowed)
__device__ float    g_cost[2][SS][BB][LL][NN];
__device__ float2   g_clslog[2][SS][BB][NN];
__device__ int      g_rows[2][SS][BB][LL];
__device__ float    g_clspart[CLSG][2][NN];     // cls partial sums (fixed slots)
__device__ float    g_regpart[2][SS][BB][LL];   // 768 floats
__device__ float    g_ioupart[2][SS][BB][LL];   // 768 floats
__device__ unsigned g_slice_cnt[NSLICE];        // monotonic (mod 21)
__device__ unsigned g_done;                     // monotonic (mod 56)

// ---------------------------------------------------------------------------
// Kernel 1 (v3): crossbar-minimal cost computation.
// 96 threads = 3 warps; warp w owns priors [32w, 32w+32).
// Lane = (slot = lane>>2, j = lane&3). Thread j caches q-chunk {j, j+4, ...}
// for ALL 4 gt-lanes in registers (read once/warp), then loops 4 steps of 8
// priors loading only its p-chunk (every LDS.128 phase = 512B distinct,
// conflict-free via row stride 80). 4-way chunk reduce via sacc (stride 20,
// conflict-free). Last chunk-block of each slice runs greedy assignment.
// ---------------------------------------------------------------------------
__global__ void __launch_bounds__(CTHR) k_cost(const float* __restrict__ pA,
                                               const float* __restrict__ pB,
                                               const float* __restrict__ gt) {
    __shared__ float sp[PRI][80];    // row: [2,3]=logits [4..7]=geo [8..79]=offs
    __shared__ float sacc[PRI * 20]; // [pr*20 + 4j] = float4(a0..a3)
    __shared__ float sq[LL][NP];     // gt offsets * (1/799)
    __shared__ float sraw4[LL][4];   // raw gt dims 2..5
    __shared__ int   s_win;
    __shared__ float swv[3];
    __shared__ int   swi[3];
    __shared__ int   chosen[LL];
    const int tid = threadIdx.x;

    const int chunk = blockIdx.x % NCHK;
    const int slice = blockIdx.x / NCHK;     // (br,s,b) id
    int t = slice;
    const int b = t % BB;  t /= BB;
    const int s = t % SS;  const int br = t / SS;
    const int n0 = chunk * PRI;
    const int nvalid = min(PRI, NN - n0);    // 96, or 80 in last chunk

    // gt staging (312 values)
    for (int i = tid; i < LL * DD; i += CTHR) {
        int l = i / DD, d = i % DD;
        float v = gt[b * LL * DD + i];
        if (d >= 6)      sq[l][d - 6]    = v * (1.0f / 799.0f);
        else if (d >= 2) sraw4[l][d - 2] = v;
    }

    // prediction staging: nvalid rows x 39 float2 -> sp[r][2 + 2c]
    const float2* p2 = (const float2*)((br ? pB : pA)
                     + ((size_t)((s * BB + b) * NN + n0)) * DD);
    {
        int r = tid / 39, c = tid - (tid / 39) * 39;
        #pragma unroll
        for (int it = 0; it < 39; it++) {    // 96*39 = 3744 = PRI*39
            if (r < nvalid) {
                float2 v = p2[r * 39 + c];
                *(float2*)&sp[r][2 + 2 * c] = v;   // 8B aligned
            }
            r += 2; c += 18;                 // 96 = 2*39 + 18
            if (c >= 39) { c -= 39; r += 1; }
        }
    }
    __syncthreads();

    const int lane = tid & 31, w = tid >> 5;
    const int slot = lane >> 2, j = lane & 3;
    const int cnt = (j < 2) ? 5 : 4;         // chunk sizes 5,5,4,4 (18 float4s)

    // q register cache: chunk {j, j+4, j+8, j+12, (j+16)} for all 4 l
    float4 q0[5], q1[5], q2[5], q3[5];
    #pragma unroll
    for (int i = 0; i < 5; i++) {
        if (i < cnt) {
            int m = 4 * (j + 4 * i);
            q0[i] = *(const float4*)&sq[0][m];
            q1[i] = *(const float4*)&sq[1][m];
            q2[i] = *(const float4*)&sq[2][m];
            q3[i] = *(const float4*)&sq[3][m];
        }
    }

    // 4 steps of 8 priors: only p-chunk loads (distinct 512B per LDS.128)
    #pragma unroll
    for (int st = 0; st < 4; st++) {
        int pr = (w << 5) + (st << 3) + slot;
        const float* row = sp[pr];
        float a0 = 0.f, a1 = 0.f, a2 = 0.f, a3 = 0.f;
        #pragma unroll
        for (int i = 0; i < 5; i++) {
            if (i < cnt) {
                float4 p4 = *(const float4*)&row[8 + 4 * (j + 4 * i)];
                a0 += fabsf(p4.x - q0[i].x) + fabsf(p4.y - q0[i].y)
                    + fabsf(p4.z - q0[i].z) + fabsf(p4.w - q0[i].w);
                a1 += fabsf(p4.x - q1[i].x) + fabsf(p4.y - q1[i].y)
                    + fabsf(p4.z - q1[i].z) + fabsf(p4.w - q1[i].w);
                a2 += fabsf(p4.x - q2[i].x) + fabsf(p4.y - q2[i].y)
                    + fabsf(p4.z - q2[i].z) + fabsf(p4.w - q2[i].w);
                a3 += fabsf(p4.x - q3[i].x) + fabsf(p4.y - q3[i].y)
                    + fabsf(p4.z - q3[i].z) + fabsf(p4.w - q3[i].w);
            }
        }
        *(float4*)&sacc[pr * 20 + 4 * j] = make_float4(a0, a1, a2, a3);
    }
    __syncwarp();   // writers/readers of sacc[pr] are the same warp

    // final per-prior pass: pr = tid (within own warp's prior range)
    {
        int pr = tid;
        if (pr < nvalid) {
            float p0 = sp[pr][2], p1 = sp[pr][3];
            float mx  = fmaxf(p0, p1);
            float e0  = __expf(p0 - mx), e1 = __expf(p1 - mx);
            float sum = e0 + e1;
            float lse = mx + __logf(sum);
            float score = __fdividef(e1, sum);

            float4 pg = *(const float4*)&sp[pr][4];
            float4 v0 = *(const float4*)&sacc[pr * 20 + 0];
            float4 v1 = *(const float4*)&sacc[pr * 20 + 4];
            float4 v2 = *(const float4*)&sacc[pr * 20 + 8];
            float4 v3 = *(const float4*)&sacc[pr * 20 + 12];
            float offs[4] = { v0.x + v1.x + v2.x + v3.x,
                              v0.y + v1.y + v2.y + v3.y,
                              v0.z + v1.z + v2.z + v3.z,
                              v0.w + v1.w + v2.w + v3.w };
            #pragma unroll
            for (int l = 0; l < LL; l++) {
                float4 t4 = *(const float4*)&sraw4[l];
                float geo = fabsf(pg.x - t4.x) + fabsf(pg.y - t4.y)
                          + fabsf(pg.z - t4.z) + fabsf(pg.w - t4.w);
                g_cost[br][s][b][l][n0 + pr] = geo + offs[l] * (1.0f / 72.0f) - score;
            }
            g_clslog[br][s][b][n0 + pr] = make_float2(p0 - lse, p1 - lse);
        }
    }

    // ---- per-slice gate: last chunk-block runs the greedy assignment ----
    __syncthreads();
    if (tid == 0) {
        __threadfence();
        unsigned old = atomicAdd(&g_slice_cnt[slice], 1u);
        s_win = ((old % NCHK) == NCHK - 1);
        if (s_win) __threadfence();
    }
    __syncthreads();
    if (!s_win) return;

    // greedy assignment without replacement (3 warps, 96 threads)
    for (int l = 0; l < LL; l++) {
        const float* cost = &g_cost[br][s][b][l][0];
        float best = INFINITY; int bi = NN;
        for (int n = tid; n < NN; n += CTHR) {
            bool used = false;
            #pragma unroll
            for (int jj = 0; jj < 3; jj++) used |= (jj < l) && (chosen[jj] == n);
            float v = used ? INFINITY : cost[n];
            if (v < best) { best = v; bi = n; }   // ascending n -> first idx tie
        }
        #pragma unroll
        for (int o = 16; o; o >>= 1) {
            float ov = __shfl_xor_sync(0xffffffffu, best, o);
            int   oi = __shfl_xor_sync(0xffffffffu, bi,   o);
            if (ov < best || (ov == best && oi < bi)) { best = ov; bi = oi; }
        }
        if (lane == 0) { swv[w] = best; swi[w] = bi; }
        __syncthreads();
        if (tid == 0) {
            float bv = swv[0]; int bix = swi[0];
            #pragma unroll
            for (int ww = 1; ww < 3; ww++) {
                if (swv[ww] < bv || (swv[ww] == bv && swi[ww] < bix)) {
                    bv = swv[ww]; bix = swi[ww];
                }
            }
            chosen[l] = bix; g_rows[br][s][b][l] = bix;
        }
        __syncthreads();
    }
}

// ---------------------------------------------------------------------------
// Kernel 2: blocks 0-31 = focal cls partials (2 br x 2 n-halves x 8 sb-groups);
// blocks 32-55 = matched partials (32 warps each); last block (monotonic
// gate) runs finalize: inst assembly in shared, scatter, dual-rank radix
// median, weighted sum.   [unchanged from round 8]
// ---------------------------------------------------------------------------
__global__ void __launch_bounds__(1024) k_rest(const float* __restrict__ pA,
                                               const float* __restrict__ pB,
                                               const float* __restrict__ gt,
                                               const float* __restrict__ diff,
                                               float* __restrict__ out) {
    __shared__ int      srows[SS * BB * LL];   // 384 (cls staging)
    __shared__ float    sinst[2 * NN];         // 16 KB (finalize)
    __shared__ float    s1[1536];              // reg/iou partial staging
    __shared__ unsigned su[NN];                // radix keys
    __shared__ int      hist[512];             // dual-track histograms
    __shared__ int      s_d0, s_k0, s_d1, s_k1;
    __shared__ float    s_med[2];
    __shared__ float    sred[1024];
    __shared__ int      s_last;
    const int tid = threadIdx.x;
    const int lane = tid & 31;

    if (blockIdx.x < 32) {
        // ---- cls partials: id = (br, nhalf, g) ----
        int id = blockIdx.x;
        int g  = id & 7;           // sb-group
        int nh = (id >> 3) & 1;    // n half
        int br = id >> 4;          // branch
        int n  = nh * 1024 + tid;

        const int* rsrc = &g_rows[br][0][0][0];
        if (tid < SS * BB * LL) srows[tid] = rsrc[tid];
        __syncthreads();

        if (n < NN) {
            const float2* lpbase = &g_clslog[br][0][0][0];
            float acc = 0.0f;
            int sb0 = g * SBPG;
            #pragma unroll
            for (int i = 0; i < SBPG; i++) {
                int sb = sb0 + i;
                float2 lp = lpbase[sb * NN + n];
                const int* r = &srows[sb * 4];
                bool matched = (r[0] == n) | (r[1] == n) | (r[2] == n) | (r[3] == n);
                float logpt = matched ? lp.y : lp.x;
                float pt = __expf(logpt);
                float a = matched ? 0.9f : 0.1f;
                float om = 1.0f - pt;
                acc += -a * om * om * logpt;
            }
            g_clspart[g][br][n] = acc;
        }
    } else {
        // ---- matched part: 32 warps/block, one (br,s,b,l) each ----
        int wib = tid >> 5;
        int id = (blockIdx.x - 32) * 32 + wib;   // [0, 768)
        int l = id % LL; int t = id / LL;
        int b = t % BB;  t /= BB;
        int s = t % SS;  int br = t / SS;

        int r = g_rows[br][s][b][l];
        const float* pm = (br ? pB : pA) + ((size_t)((s * BB + b) * NN + r)) * DD;
        const float* tg = gt + (b * LL + l) * DD;

        float sl = 0.0f;
        if (lane < 4) {
            const float scv[4] = {71.0f, 799.0f, 180.0f, 71.0f};
            float d = pm[2 + lane] * scv[lane] - tg[2 + lane] * scv[lane];
            float ad = fabsf(d);
            sl = (ad < 1.0f) ? 0.5f * d * d : ad - 0.5f;
        }
        float ovr = 0.0f, uni = 0.0f;
        #pragma unroll
        for (int jj = 0; jj < 3; jj++) {
            int j = lane + jj * 32;
            if (j < NP) {
                float rp = pm[6 + j] * 799.0f;
                float rt = tg[6 + j];
                bool inv = (rt < 0.0f) || (rt >= 800.0f);
                float o = fminf(rp + 15.0f, rt + 15.0f) - fmaxf(rp - 15.0f, rt - 15.0f);
                float u = fmaxf(rp + 15.0f, rt + 15.0f) - fminf(rp - 15.0f, rt - 15.0f);
                if (!inv) { ovr += o; uni += u; }
            }
        }
        #pragma unroll
        for (int o = 16; o; o >>= 1) {
            sl  += __shfl_xor_sync(0xffffffffu, sl,  o);
            ovr += __shfl_xor_sync(0xffffffffu, ovr, o);
            uni += __shfl_xor_sync(0xffffffffu, uni, o);
        }
        if (lane == 0) {
            float iou = ovr / (uni + 1e-9f);
            g_regpart[br][s][b][l] = (sl * 0.25f) / (float)LL;
            g_ioupart[br][s][b][l] = (1.0f - iou) / (float)LL;
        }
    }

    // ---- last-block gate (monotonic counter, no reset needed) ----
    __syncthreads();
    if (tid == 0) {
        __threadfence();
        unsigned old = atomicAdd(&g_done, 1u);
        s_last = ((old % (unsigned)NBLK2) == NBLK2 - 1u);
        if (s_last) __threadfence();
    }
    __syncthreads();
    if (!s_last) return;

    // ================= finalize (1024 threads) ===============================
    for (int n = tid; n < NN; n += 1024) {
        float a0 = 0.0f, a1 = 0.0f;
        #pragma unroll
        for (int g = 0; g < CLSG; g++) {
            a0 += g_clspart[g][0][n];
            a1 += g_clspart[g][1][n];
        }
        sinst[n]      = a0 * (1.0f / 96.0f) * 2.0f;
        sinst[NN + n] = a1 * (1.0f / 96.0f) * 2.0f;
    }
    if (tid < 768) {
        s1[tid]       = (&g_regpart[0][0][0][0])[tid];
        s1[768 + tid] = (&g_ioupart[0][0][0][0])[tid];
    }
    __syncthreads();
    if (tid < 2 * LL) {
        int br = tid >> 2, l = tid & 3;
        float rs = 0.0f, is = 0.0f;
        int base = br * 384 + l;
        #pragma unroll 8
        for (int sb = 0; sb < SS * BB; sb++) {
            rs += s1[base + sb * 4];
            is += s1[768 + base + sb * 4];
        }
        rs *= (1.0f / 96.0f);
        is *= (1.0f / 96.0f);
        int row = g_rows[br][SS - 1][BB - 1][l];
        sinst[br * NN + row] += rs * 0.5f + is * 2.0f;  // REG_W, IOU_W
    }
    __syncthreads();

    for (int n = tid; n < NN; n += 1024) {
        float x = sinst[n] - sinst[NN + n];
        unsigned u = __float_as_uint(x);
        su[n] = (u & 0x80000000u) ? ~u : (u | 0x80000000u);
    }
    __syncthreads();

    // dual-rank radix select (ranks 999 & 1000 in one sweep, 4 levels)
    {
        int k0 = 999, k1 = 1000;
        unsigned pf0 = 0, pf1 = 0;
        for (int shift = 24; shift >= 0; shift -= 8) {
            unsigned mask = (shift == 24) ? 0u : (0xFFFFFFFFu << (shift + 8));
            bool eq = (pf0 == pf1);
            if (tid < 512) hist[tid] = 0;
            __syncthreads();
            #pragma unroll
            for (int it = 0; it < 2; it++) {
                int i = tid + it * 1024;
                unsigned u = (i < NN) ? su[i] : 0u;
                bool act = (i < NN);
                unsigned m = u & mask;
                int d = (int)((u >> shift) & 255);
                int bin0 = (act && m == pf0) ? d : 512;
                unsigned mm0 = __match_any_sync(0xffffffffu, bin0);
                if (bin0 < 512 && lane == (__ffs(mm0) - 1))
                    atomicAdd(&hist[bin0], __popc(mm0));
                if (!eq) {
                    int bin1 = (act && m == pf1) ? 256 + d : 512;
                    unsigned mm1 = __match_any_sync(0xffffffffu, bin1);
                    if (bin1 < 512 && lane == (__ffs(mm1) - 1))
                        atomicAdd(&hist[bin1], __popc(mm1));
                }
            }
            __syncthreads();
            if (tid < 32) {
                int base = tid * 8, ssum = 0;
                int c[8];
                #pragma unroll
                for (int jj = 0; jj < 8; jj++) { c[jj] = hist[base + jj]; ssum += c[jj]; }
                int run = ssum;
                #pragma unroll
                for (int o = 1; o < 32; o <<= 1) {
                    int v = __shfl_up_sync(0xffffffffu, run, o);
                    if (lane >= o) run += v;
                }
                int excl = run - ssum;
                if (k0 >= excl && k0 < run) {
                    int a2 = excl;
                    #pragma unroll
                    for (int jj = 0; jj < 8; jj++) {
                        if (k0 < a2 + c[jj]) { s_d0 = base + jj; s_k0 = k0 - a2; break; }
                        a2 += c[jj];
                    }
                }
                if (eq && k1 >= excl && k1 < run) {
                    int a2 = excl;
                    #pragma unroll
                    for (int jj = 0; jj < 8; jj++) {
                        if (k1 < a2 + c[jj]) { s_d1 = base + jj; s_k1 = k1 - a2; break; }
                        a2 += c[jj];
                    }
                }
            } else if (tid >= 32 && tid < 64 && !eq) {
                int l2 = tid - 32;
                int base = 256 + l2 * 8, ssum = 0;
                int c[8];
                #pragma unroll
                for (int jj = 0; jj < 8; jj++) { c[jj] = hist[base + jj]; ssum += c[jj]; }
                int run = ssum;
                #pragma unroll
                for (int o = 1; o < 32; o <<= 1) {
                    int v = __shfl_up_sync(0xffffffffu, run, o);
                    if (l2 >= o) run += v;
                }
                int excl = run - ssum;
                if (k1 >= excl && k1 < run) {
                    int a2 = excl;
                    #pragma unroll
                    for (int jj = 0; jj < 8; jj++) {
                        if (k1 < a2 + c[jj]) { s_d1 = base - 256 + jj; s_k1 = k1 - a2; break; }
                        a2 += c[jj];
                    }
                }
            }
            __syncthreads();
            pf0 |= ((unsigned)s_d0) << shift;  k0 = s_k0;
            pf1 |= ((unsigned)s_d1) << shift;  k1 = s_k1;
        }
        if (tid == 0) {
            unsigned u0 = pf0, u1 = pf1;
            s_med[0] = (u0 & 0x80000000u) ? __uint_as_float(u0 ^ 0x80000000u)
                                          : __uint_as_float(~u0);
            s_med[1] = (u1 & 0x80000000u) ? __uint_as_float(u1 ^ 0x80000000u)
                                          : __uint_as_float(~u1);
        }
        __syncthreads();
    }
    float delta = 0.5f * (s_med[0] + s_med[1]);

    float acc = 0.0f;
    for (int n = tid; n < NN; n += 1024) {
        float dm = (diff[n] + diff[NN + n] + diff[2 * NN + n]) * (1.0f / 3.0f);
        acc += (1.0f - dm) * (sinst[n] - 0.5f * delta)
             + dm * (sinst[NN + n] + 0.5f * delta);
    }
    sred[tid] = acc;
    __syncthreads();
    for (int o = 512; o; o >>= 1) {
        if (tid < o) sred[tid] += sred[tid + o];
        __syncthreads();
    }
    if (tid == 0) out[0] = sred[0];
}

// ---------------------------------------------------------------------------
extern "C" void kernel_launch(void* const* d_in, const int* in_sizes, int n_in,
                              void* d_out, int out_size) {
    const float* pA   = (const float*)d_in[0];  // predictions_fir [S,B,N,D]
    const float* pB   = (const float*)d_in[1];  // predictions_sec [S,B,N,D]
    const float* gt   = (const float*)d_in[2];  // gt_lane [B,L,D]
    const float* diff = (const float*)d_in[3];  // diff [S,N]
    float* out = (float*)d_out;

    k_cost<<<NSLICE * NCHK, CTHR>>>(pA, pB, gt);     // 4032 blocks, assign inline
    k_rest<<<NBLK2, 1024>>>(pA, pB, gt, diff, out);  // cls+matched+finalize
}

// round 10
// speedup vs baseline: 1.0579x; 1.0579x over previous
#include <cuda_runtime.h>
#include <math.h>

// Problem constants
#define SS 3       // REFINE_LAYERS
#define BB 32      // batch
#define NN 2000    // priors
#define LL 4       // max lanes
#define DD 78      // 2 + 4 + 72
#define NP 72      // num points offsets
#define PRI 80     // priors per k_cost block
#define NCHK (NN / PRI)        // 25 chunk-blocks per slice
#define NSLICE (2 * SS * BB)   // 192

// Scratch (device globals; no allocation allowed)
__device__ float    g_cost[2][SS][BB][LL][NN];
__device__ float2   g_clslog[2][SS][BB][NN];
__device__ int      g_rows[2][SS][BB][LL];
__device__ float    g_clspart[2][SS * BB][NN];  // per-slice focal terms
__device__ float    g_inst[2][NN];
__device__ float    g_regpart[2][SS][BB][LL];   // 768 floats
__device__ float    g_ioupart[2][SS][BB][LL];   // 768 floats
__device__ unsigned g_slice_cnt[NSLICE];        // monotonic (mod 25)

// ---------------------------------------------------------------------------
// Kernel 1: cost matrix + log-softmax (round-8 core). The last chunk-block
// of each slice (per-slice monotonic counter) then runs, INLINE: greedy
// assignment, this slice's focal cls terms, and matched reg/iou partials.
// ---------------------------------------------------------------------------
__global__ void __launch_bounds__(320) k_cost(const float* __restrict__ pA,
                                              const float* __restrict__ pB,
                                              const float* __restrict__ gt) {
    __shared__ float sp[PRI][84];   // prediction rows, dims at [2..79]
    __shared__ float sq[LL][NP];    // gt offsets * (1/799)
    __shared__ float sraw[LL][4];   // raw gt dims 2..5
    __shared__ int   s_win;
    __shared__ float swv[10];
    __shared__ int   swi[10];
    __shared__ int   chosen[LL];
    const int tid = threadIdx.x;

    const int chunk = blockIdx.x % NCHK;
    const int slice = blockIdx.x / NCHK;     // (br,s,b) id
    int t = slice;
    const int b = t % BB;  t /= BB;
    const int s = t % SS;  const int br = t / SS;
    const int n0 = chunk * PRI;

    // gt staging (312 values)
    for (int i = tid; i < LL * DD; i += 320) {
        int l = i / DD, d = i % DD;
        float v = gt[b * LL * DD + i];
        if (d >= 6)      sq[l][d - 6]   = v * (1.0f / 799.0f);
        else if (d >= 2) sraw[l][d - 2] = v;
    }
    // prediction staging: 80 rows x 39 float2; incremental row/col stepping
    const float* predbase = (br ? pB : pA) + ((size_t)((s * BB + b) * NN)) * DD;
    const float2* p2 = (const float2*)(predbase + (size_t)n0 * DD);
    {
        int r = tid / 39;
        int c = tid - r * 39;
        #pragma unroll
        for (int it = 0; it < 10; it++) {     // 3120 float2 over 320 threads
            int i = tid + it * 320;
            if (i < PRI * DD / 2) {
                float2 v = p2[i];
                *(float2*)&sp[r][2 + 2 * c] = v;
            }
            c += 8; r += 8;                   // 320 = 8*39 + 8
            if (c >= 39) { c -= 39; r += 1; }
        }
    }
    __syncthreads();

    {
        int pr = tid >> 2, l = tid & 3;
        float p0 = sp[pr][2], p1 = sp[pr][3];
        float mx  = fmaxf(p0, p1);
        float e0  = __expf(p0 - mx), e1 = __expf(p1 - mx);
        float sum = e0 + e1;
        float lse = mx + __logf(sum);
        float score = __fdividef(e1, sum);

        float4 g4 = *(const float4*)&sp[pr][4];    // dims 2..5
        float4 t4 = *(const float4*)&sraw[l][0];
        float geo = fabsf(g4.x - t4.x) + fabsf(g4.y - t4.y)
                  + fabsf(g4.z - t4.z) + fabsf(g4.w - t4.w);

        float off = 0.0f;
        #pragma unroll
        for (int k = 0; k < NP / 4; k++) {
            float4 a = *(const float4*)&sp[pr][8 + 4 * k];
            float4 q = *(const float4*)&sq[l][4 * k];
            off += fabsf(a.x - q.x) + fabsf(a.y - q.y)
                 + fabsf(a.z - q.z) + fabsf(a.w - q.w);
        }
        g_cost[br][s][b][l][n0 + pr] = geo + off * (1.0f / 72.0f) - score;
        if (l == 0)
            g_clslog[br][s][b][n0 + pr] = make_float2(p0 - lse, p1 - lse);
    }

    // ---- per-slice gate: last chunk-block runs assignment + cls + matched --
    __syncthreads();
    if (tid == 0) {
        __threadfence();
        unsigned old = atomicAdd(&g_slice_cnt[slice], 1u);
        s_win = ((old % NCHK) == NCHK - 1);
        if (s_win) __threadfence();
    }
    __syncthreads();
    if (!s_win) return;

    // greedy assignment without replacement (10 warps, 320 threads)
    const int wib = tid >> 5, lane = tid & 31;
    for (int l = 0; l < LL; l++) {
        const float* cost = &g_cost[br][s][b][l][0];
        float best = INFINITY; int bi = NN;
        for (int n = tid; n < NN; n += 320) {
            bool used = false;
            #pragma unroll
            for (int j = 0; j < 3; j++) used |= (j < l) && (chosen[j] == n);
            float v = used ? INFINITY : cost[n];
            if (v < best) { best = v; bi = n; }   // ascending n -> first idx tie
        }
        #pragma unroll
        for (int o = 16; o; o >>= 1) {
            float ov = __shfl_xor_sync(0xffffffffu, best, o);
            int   oi = __shfl_xor_sync(0xffffffffu, bi,   o);
            if (ov < best || (ov == best && oi < bi)) { best = ov; bi = oi; }
        }
        if (lane == 0) { swv[wib] = best; swi[wib] = bi; }
        __syncthreads();
        if (tid == 0) {
            float bv = swv[0]; int bix = swi[0];
            #pragma unroll
            for (int w = 1; w < 10; w++) {
                if (swv[w] < bv || (swv[w] == bv && swi[w] < bix)) {
                    bv = swv[w]; bix = swi[w];
                }
            }
            chosen[l] = bix; g_rows[br][s][b][l] = bix;
        }
        __syncthreads();
    }

    // ---- inline cls: this slice's focal terms (unscaled) ----
    {
        const float2* lp = &g_clslog[br][s][b][0];
        float* dst = &g_clspart[br][s * BB + b][0];
        int c0 = chosen[0], c1 = chosen[1], c2 = chosen[2], c3 = chosen[3];
        #pragma unroll
        for (int it = 0; it < 7; it++) {      // 7*320 = 2240 >= 2000
            int n = tid + it * 320;
            if (n < NN) {
                float2 v = lp[n];
                bool matched = (c0 == n) | (c1 == n) | (c2 == n) | (c3 == n);
                float logpt = matched ? v.y : v.x;
                float pt = __expf(logpt);
                float a = matched ? 0.9f : 0.1f;
                float om = 1.0f - pt;
                dst[n] = -a * om * om * logpt;
            }
        }
    }

    // ---- inline matched: warps 0-3, one l each ----
    if (wib < LL) {
        int l = wib;
        int r = chosen[l];
        const float* pm = predbase + (size_t)r * DD;
        const float* tg = gt + (b * LL + l) * DD;

        float sl = 0.0f;
        if (lane < 4) {
            const float scv[4] = {71.0f, 799.0f, 180.0f, 71.0f};
            float d = pm[2 + lane] * scv[lane] - tg[2 + lane] * scv[lane];
            float ad = fabsf(d);
            sl = (ad < 1.0f) ? 0.5f * d * d : ad - 0.5f;
        }
        float ovr = 0.0f, uni = 0.0f;
        #pragma unroll
        for (int jj = 0; jj < 3; jj++) {
            int j = lane + jj * 32;
            if (j < NP) {
                float rp = pm[6 + j] * 799.0f;
                float rt = tg[6 + j];
                bool inv = (rt < 0.0f) || (rt >= 800.0f);
                float o = fminf(rp + 15.0f, rt + 15.0f) - fmaxf(rp - 15.0f, rt - 15.0f);
                float u = fmaxf(rp + 15.0f, rt + 15.0f) - fminf(rp - 15.0f, rt - 15.0f);
                if (!inv) { ovr += o; uni += u; }
            }
        }
        #pragma unroll
        for (int o = 16; o; o >>= 1) {
            sl  += __shfl_xor_sync(0xffffffffu, sl,  o);
            ovr += __shfl_xor_sync(0xffffffffu, ovr, o);
            uni += __shfl_xor_sync(0xffffffffu, uni, o);
        }
        if (lane == 0) {
            float iou = ovr / (uni + 1e-9f);
            g_regpart[br][s][b][l] = (sl * 0.25f) / (float)LL;
            g_ioupart[br][s][b][l] = (1.0f - iou) / (float)LL;
        }
    }
}

// ---------------------------------------------------------------------------
// Kernel 2: reduce cls partials over the 96 sb (ascending order = reference
// association) -> g_inst. 16 blocks x 256 threads; coalesced, L2-resident.
// ---------------------------------------------------------------------------
__global__ void __launch_bounds__(256) k_reduce() {
    int br  = blockIdx.x >> 3;
    int oct = blockIdx.x & 7;
    int n   = oct * 250 + threadIdx.x;
    if (threadIdx.x >= 250) return;

    const float* src = &g_clspart[br][0][0];
    float acc = 0.0f;
    #pragma unroll 8
    for (int sb = 0; sb < SS * BB; sb++)
        acc += src[sb * NN + n];
    g_inst[br][n] = acc * (1.0f / 96.0f) * 2.0f;   // /(B*S), * CLS_W
}

// ---------------------------------------------------------------------------
// Kernel 3: finalize (1 block, 1024 threads). Load inst, scatter reg/iou,
// dual-rank radix-select median (exact order stats), weighted sum.
// ---------------------------------------------------------------------------
__global__ void __launch_bounds__(1024) k_final(const float* __restrict__ diff,
                                                float* __restrict__ out) {
    __shared__ float    sinst[2 * NN];         // 16 KB
    __shared__ float    s1[1536];              // reg/iou partial staging
    __shared__ unsigned su[NN];                // radix keys
    __shared__ int      hist[512];             // dual-track histograms
    __shared__ int      s_d0, s_k0, s_d1, s_k1;
    __shared__ float    s_med[2];
    __shared__ float    sred[1024];
    const int tid = threadIdx.x;
    const int lane = tid & 31;

    // load inst
    for (int n = tid; n < NN; n += 1024) {
        sinst[n]      = g_inst[0][n];
        sinst[NN + n] = g_inst[1][n];
    }
    // stage reg/iou partials
    if (tid < 768) {
        s1[tid]       = (&g_regpart[0][0][0][0])[tid];
        s1[768 + tid] = (&g_ioupart[0][0][0][0])[tid];
    }
    __syncthreads();
    if (tid < 2 * LL) {
        int br = tid >> 2, l = tid & 3;
        float rs = 0.0f, is = 0.0f;
        int base = br * 384 + l;
        #pragma unroll 8
        for (int sb = 0; sb < SS * BB; sb++) {
            rs += s1[base + sb * 4];
            is += s1[768 + base + sb * 4];
        }
        rs *= (1.0f / 96.0f);
        is *= (1.0f / 96.0f);
        int row = g_rows[br][SS - 1][BB - 1][l];
        sinst[br * NN + row] += rs * 0.5f + is * 2.0f;  // REG_W, IOU_W
    }
    __syncthreads();

    // order-preserving uint keys of x = instA - instB
    for (int n = tid; n < NN; n += 1024) {
        float x = sinst[n] - sinst[NN + n];
        unsigned u = __float_as_uint(x);
        su[n] = (u & 0x80000000u) ? ~u : (u | 0x80000000u);
    }
    __syncthreads();

    // dual-rank radix select (ranks 999 & 1000 in one sweep, 4 levels)
    {
        int k0 = 999, k1 = 1000;
        unsigned pf0 = 0, pf1 = 0;
        for (int shift = 24; shift >= 0; shift -= 8) {
            unsigned mask = (shift == 24) ? 0u : (0xFFFFFFFFu << (shift + 8));
            bool eq = (pf0 == pf1);
            if (tid < 512) hist[tid] = 0;
            __syncthreads();
            #pragma unroll
            for (int it = 0; it < 2; it++) {
                int i = tid + it * 1024;
                unsigned u = (i < NN) ? su[i] : 0u;
                bool act = (i < NN);
                unsigned m = u & mask;
                int d = (int)((u >> shift) & 255);
                int bin0 = (act && m == pf0) ? d : 512;
                unsigned mm0 = __match_any_sync(0xffffffffu, bin0);
                if (bin0 < 512 && lane == (__ffs(mm0) - 1))
                    atomicAdd(&hist[bin0], __popc(mm0));
                if (!eq) {
                    int bin1 = (act && m == pf1) ? 256 + d : 512;
                    unsigned mm1 = __match_any_sync(0xffffffffu, bin1);
                    if (bin1 < 512 && lane == (__ffs(mm1) - 1))
                        atomicAdd(&hist[bin1], __popc(mm1));
                }
            }
            __syncthreads();
            if (tid < 32) {
                int base = tid * 8, ssum = 0;
                int c[8];
                #pragma unroll
                for (int jj = 0; jj < 8; jj++) { c[jj] = hist[base + jj]; ssum += c[jj]; }
                int run = ssum;
                #pragma unroll
                for (int o = 1; o < 32; o <<= 1) {
                    int v = __shfl_up_sync(0xffffffffu, run, o);
                    if (lane >= o) run += v;
                }
                int excl = run - ssum;
                if (k0 >= excl && k0 < run) {
                    int a2 = excl;
                    #pragma unroll
                    for (int jj = 0; jj < 8; jj++) {
                        if (k0 < a2 + c[jj]) { s_d0 = base + jj; s_k0 = k0 - a2; break; }
                        a2 += c[jj];
                    }
                }
                if (eq && k1 >= excl && k1 < run) {
                    int a2 = excl;
                    #pragma unroll
                    for (int jj = 0; jj < 8; jj++) {
                        if (k1 < a2 + c[jj]) { s_d1 = base + jj; s_k1 = k1 - a2; break; }
                        a2 += c[jj];
                    }
                }
            } else if (tid >= 32 && tid < 64 && !eq) {
                int l2 = tid - 32;
                int base = 256 + l2 * 8, ssum = 0;
                int c[8];
                #pragma unroll
                for (int jj = 0; jj < 8; jj++) { c[jj] = hist[base + jj]; ssum += c[jj]; }
                int run = ssum;
                #pragma unroll
                for (int o = 1; o < 32; o <<= 1) {
                    int v = __shfl_up_sync(0xffffffffu, run, o);
                    if (l2 >= o) run += v;
                }
                int excl = run - ssum;
                if (k1 >= excl && k1 < run) {
                    int a2 = excl;
                    #pragma unroll
                    for (int jj = 0; jj < 8; jj++) {
                        if (k1 < a2 + c[jj]) { s_d1 = base - 256 + jj; s_k1 = k1 - a2; break; }
                        a2 += c[jj];
                    }
                }
            }
            __syncthreads();
            pf0 |= ((unsigned)s_d0) << shift;  k0 = s_k0;
            pf1 |= ((unsigned)s_d1) << shift;  k1 = s_k1;
        }
        if (tid == 0) {
            unsigned u0 = pf0, u1 = pf1;
            s_med[0] = (u0 & 0x80000000u) ? __uint_as_float(u0 ^ 0x80000000u)
                                          : __uint_as_float(~u0);
            s_med[1] = (u1 & 0x80000000u) ? __uint_as_float(u1 ^ 0x80000000u)
                                          : __uint_as_float(~u1);
        }
        __syncthreads();
    }
    float delta = 0.5f * (s_med[0] + s_med[1]);

    // total = sum (1-dm)*(A - d/2) + dm*(B + d/2)
    float acc = 0.0f;
    for (int n = tid; n < NN; n += 1024) {
        float dm = (diff[n] + diff[NN + n] + diff[2 * NN + n]) * (1.0f / 3.0f);
        acc += (1.0f - dm) * (sinst[n] - 0.5f * delta)
             + dm * (sinst[NN + n] + 0.5f * delta);
    }
    sred[tid] = acc;
    __syncthreads();
    for (int o = 512; o; o >>= 1) {
        if (tid < o) sred[tid] += sred[tid + o];
        __syncthreads();
    }
    if (tid == 0) out[0] = sred[0];
}

// ---------------------------------------------------------------------------
extern "C" void kernel_launch(void* const* d_in, const int* in_sizes, int n_in,
                              void* d_out, int out_size) {
    const float* pA   = (const float*)d_in[0];  // predictions_fir [S,B,N,D]
    const float* pB   = (const float*)d_in[1];  // predictions_sec [S,B,N,D]
    const float* gt   = (const float*)d_in[2];  // gt_lane [B,L,D]
    const float* diff = (const float*)d_in[3];  // diff [S,N]
    float* out = (float*)d_out;

    k_cost<<<NSLICE * NCHK, 320>>>(pA, pB, gt);  // 4800 blocks; assign+cls+matched inline
    k_reduce<<<16, 256>>>();                     // inst assembly
    k_final<<<1, 1024>>>(diff, out);             // median + weighted sum
}

// round 11
// speedup vs baseline: 1.1201x; 1.0588x over previous
#include <cuda_runtime.h>
#include <math.h>

// Problem constants
#define SS 3       // REFINE_LAYERS
#define BB 32      // batch
#define NN 2000    // priors
#define LL 4       // max lanes
#define DD 78      // 2 + 4 + 72
#define NP 72      // num points offsets
#define PRI 80     // priors per k_cost block
#define NCHK (NN / PRI)        // 25 chunk-blocks per slice
#define NSLICE (2 * SS * BB)   // 192
#define CLSG 8     // sb-groups for cls partials
#define SBPG (SS * BB / CLSG)  // 12 sb per group
#define NBLK2 56   // blocks in kernel 2 (32 cls + 24 matched)

// Scratch (device globals; no allocation allowed)
__device__ float    g_cost[2][SS][BB][LL][NN];
__device__ float2   g_clslog[2][SS][BB][NN];
__device__ int      g_rows[2][SS][BB][LL];
__device__ float    g_clspart[CLSG][2][NN];     // cls partial sums (fixed slots)
__device__ float    g_regpart[2][SS][BB][LL];   // 768 floats
__device__ float    g_ioupart[2][SS][BB][LL];   // 768 floats
__device__ unsigned g_slice_cnt[NSLICE];        // monotonic (mod 25)
__device__ unsigned g_done;                     // monotonic (mod 56)

// ---------------------------------------------------------------------------
// Kernel 1: cost matrix + log-softmax. Thread mapping pr = tid%80, l = tid/80:
// a warp = 32 consecutive priors at fixed l -> p-row LDS.128 are 100% distinct
// bytes (bank step 20 = perfect 32-bank partition per phase), q loads are
// full-warp broadcast, cost/clslog stores fully coalesced. Last chunk-block
// of each slice (monotonic counter) runs the greedy assignment inline.
// ---------------------------------------------------------------------------
__global__ void __launch_bounds__(320) k_cost(const float* __restrict__ pA,
                                              const float* __restrict__ pB,
                                              const float* __restrict__ gt) {
    __shared__ float sp[PRI][84];   // prediction rows, dims at [2..79]
    __shared__ float sq[LL][NP];    // gt offsets * (1/799)
    __shared__ float sraw[LL][4];   // raw gt dims 2..5
    __shared__ int   s_win;
    __shared__ float swv[10];
    __shared__ int   swi[10];
    __shared__ int   chosen[LL];
    const int tid = threadIdx.x;

    const int chunk = blockIdx.x % NCHK;
    const int slice = blockIdx.x / NCHK;     // (br,s,b) id
    int t = slice;
    const int b = t % BB;  t /= BB;
    const int s = t % SS;  const int br = t / SS;
    const int n0 = chunk * PRI;

    // gt staging (312 values)
    for (int i = tid; i < LL * DD; i += 320) {
        int l = i / DD, d = i % DD;
        float v = gt[b * LL * DD + i];
        if (d >= 6)      sq[l][d - 6]   = v * (1.0f / 799.0f);
        else if (d >= 2) sraw[l][d - 2] = v;
    }
    // prediction staging: 80 rows x 39 float2; incremental row/col stepping
    const float2* p2 = (const float2*)((br ? pB : pA)
                     + ((size_t)((s * BB + b) * NN + n0)) * DD);
    {
        int r = tid / 39;
        int c = tid - r * 39;
        #pragma unroll
        for (int it = 0; it < 10; it++) {     // 3120 float2 over 320 threads
            int i = tid + it * 320;
            if (i < PRI * DD / 2) {
                float2 v = p2[i];
                *(float2*)&sp[r][2 + 2 * c] = v;
            }
            c += 8; r += 8;                   // 320 = 8*39 + 8
            if (c >= 39) { c -= 39; r += 1; }
        }
    }
    __syncthreads();

    {
        int pr = tid % PRI, l = tid / PRI;    // warp = 32 consecutive priors, fixed l
        float p0 = sp[pr][2], p1 = sp[pr][3];
        float mx  = fmaxf(p0, p1);
        float e0  = __expf(p0 - mx), e1 = __expf(p1 - mx);
        float sum = e0 + e1;
        float lse = mx + __logf(sum);
        float score = __fdividef(e1, sum);

        float4 g4 = *(const float4*)&sp[pr][4];    // dims 2..5
        float4 t4 = *(const float4*)&sraw[l][0];
        float geo = fabsf(g4.x - t4.x) + fabsf(g4.y - t4.y)
                  + fabsf(g4.z - t4.z) + fabsf(g4.w - t4.w);

        float off = 0.0f;
        #pragma unroll
        for (int k = 0; k < NP / 4; k++) {
            float4 a = *(const float4*)&sp[pr][8 + 4 * k];
            float4 q = *(const float4*)&sq[l][4 * k];
            off += fabsf(a.x - q.x) + fabsf(a.y - q.y)
                 + fabsf(a.z - q.z) + fabsf(a.w - q.w);
        }
        g_cost[br][s][b][l][n0 + pr] = geo + off * (1.0f / 72.0f) - score;  // coalesced
        if (l == 0)
            g_clslog[br][s][b][n0 + pr] = make_float2(p0 - lse, p1 - lse);  // coalesced
    }

    // ---- per-slice gate: last chunk-block runs the greedy assignment ----
    __syncthreads();
    if (tid == 0) {
        __threadfence();
        unsigned old = atomicAdd(&g_slice_cnt[slice], 1u);
        s_win = ((old % NCHK) == NCHK - 1);
        if (s_win) __threadfence();
    }
    __syncthreads();
    if (!s_win) return;

    // greedy assignment without replacement (10 warps, 320 threads)
    const int wib = tid >> 5, lane = tid & 31;
    for (int l = 0; l < LL; l++) {
        const float* cost = &g_cost[br][s][b][l][0];
        float best = INFINITY; int bi = NN;
        for (int n = tid; n < NN; n += 320) {
            bool used = false;
            #pragma unroll
            for (int j = 0; j < 3; j++) used |= (j < l) && (chosen[j] == n);
            float v = used ? INFINITY : cost[n];
            if (v < best) { best = v; bi = n; }   // ascending n -> first idx tie
        }
        #pragma unroll
        for (int o = 16; o; o >>= 1) {
            float ov = __shfl_xor_sync(0xffffffffu, best, o);
            int   oi = __shfl_xor_sync(0xffffffffu, bi,   o);
            if (ov < best || (ov == best && oi < bi)) { best = ov; bi = oi; }
        }
        if (lane == 0) { swv[wib] = best; swi[wib] = bi; }
        __syncthreads();
        if (tid == 0) {
            float bv = swv[0]; int bix = swi[0];
            #pragma unroll
            for (int w = 1; w < 10; w++) {
                if (swv[w] < bv || (swv[w] == bv && swi[w] < bix)) {
                    bv = swv[w]; bix = swi[w];
                }
            }
            chosen[l] = bix; g_rows[br][s][b][l] = bix;
        }
        __syncthreads();
    }
}

// ---------------------------------------------------------------------------
// Kernel 2 (round-8, unchanged): blocks 0-31 = focal cls partials
// (2 br x 2 n-halves x 8 sb-groups); blocks 32-55 = matched partials
// (32 warps each); last block (monotonic gate) runs finalize.
// ---------------------------------------------------------------------------
__global__ void __launch_bounds__(1024) k_rest(const float* __restrict__ pA,
                                               const float* __restrict__ pB,
                                               const float* __restrict__ gt,
                                               const float* __restrict__ diff,
                                               float* __restrict__ out) {
    __shared__ int      srows[SS * BB * LL];   // 384 (cls staging)
    __shared__ float    sinst[2 * NN];         // 16 KB (finalize)
    __shared__ float    s1[1536];              // reg/iou partial staging
    __shared__ unsigned su[NN];                // radix keys
    __shared__ int      hist[512];             // dual-track histograms
    __shared__ int      s_d0, s_k0, s_d1, s_k1;
    __shared__ float    s_med[2];
    __shared__ float    sred[1024];
    __shared__ int      s_last;
    const int tid = threadIdx.x;
    const int lane = tid & 31;

    if (blockIdx.x < 32) {
        // ---- cls partials: id = (br, nhalf, g) ----
        int id = blockIdx.x;
        int g  = id & 7;           // sb-group
        int nh = (id >> 3) & 1;    // n half
        int br = id >> 4;          // branch
        int n  = nh * 1024 + tid;

        const int* rsrc = &g_rows[br][0][0][0];
        if (tid < SS * BB * LL) srows[tid] = rsrc[tid];
        __syncthreads();

        if (n < NN) {
            const float2* lpbase = &g_clslog[br][0][0][0];
            float acc = 0.0f;
            int sb0 = g * SBPG;
            #pragma unroll
            for (int i = 0; i < SBPG; i++) {
                int sb = sb0 + i;
                float2 lp = lpbase[sb * NN + n];
                const int* r = &srows[sb * 4];
                bool matched = (r[0] == n) | (r[1] == n) | (r[2] == n) | (r[3] == n);
                float logpt = matched ? lp.y : lp.x;
                float pt = __expf(logpt);
                float a = matched ? 0.9f : 0.1f;
                float om = 1.0f - pt;
                acc += -a * om * om * logpt;
            }
            g_clspart[g][br][n] = acc;
        }
    } else {
        // ---- matched part: 32 warps/block, one (br,s,b,l) each ----
        int wib = tid >> 5;
        int id = (blockIdx.x - 32) * 32 + wib;   // [0, 768)
        int l = id % LL; int t = id / LL;
        int b = t % BB;  t /= BB;
        int s = t % SS;  int br = t / SS;

        int r = g_rows[br][s][b][l];
        const float* pm = (br ? pB : pA) + ((size_t)((s * BB + b) * NN + r)) * DD;
        const float* tg = gt + (b * LL + l) * DD;

        float sl = 0.0f;
        if (lane < 4) {
            const float scv[4] = {71.0f, 799.0f, 180.0f, 71.0f};
            float d = pm[2 + lane] * scv[lane] - tg[2 + lane] * scv[lane];
            float ad = fabsf(d);
            sl = (ad < 1.0f) ? 0.5f * d * d : ad - 0.5f;
        }
        float ovr = 0.0f, uni = 0.0f;
        #pragma unroll
        for (int jj = 0; jj < 3; jj++) {
            int j = lane + jj * 32;
            if (j < NP) {
                float rp = pm[6 + j] * 799.0f;
                float rt = tg[6 + j];
                bool inv = (rt < 0.0f) || (rt >= 800.0f);
                float o = fminf(rp + 15.0f, rt + 15.0f) - fmaxf(rp - 15.0f, rt - 15.0f);
                float u = fmaxf(rp + 15.0f, rt + 15.0f) - fminf(rp - 15.0f, rt - 15.0f);
                if (!inv) { ovr += o; uni += u; }
            }
        }
        #pragma unroll
        for (int o = 16; o; o >>= 1) {
            sl  += __shfl_xor_sync(0xffffffffu, sl,  o);
            ovr += __shfl_xor_sync(0xffffffffu, ovr, o);
            uni += __shfl_xor_sync(0xffffffffu, uni, o);
        }
        if (lane == 0) {
            float iou = ovr / (uni + 1e-9f);
            g_regpart[br][s][b][l] = (sl * 0.25f) / (float)LL;
            g_ioupart[br][s][b][l] = (1.0f - iou) / (float)LL;
        }
    }

    // ---- last-block gate (monotonic counter, no reset needed) ----
    __syncthreads();
    if (tid == 0) {
        __threadfence();
        unsigned old = atomicAdd(&g_done, 1u);
        s_last = ((old % (unsigned)NBLK2) == NBLK2 - 1u);
        if (s_last) __threadfence();
    }
    __syncthreads();
    if (!s_last) return;

    // ================= finalize (1024 threads) ===============================
    for (int n = tid; n < NN; n += 1024) {
        float a0 = 0.0f, a1 = 0.0f;
        #pragma unroll
        for (int g = 0; g < CLSG; g++) {
            a0 += g_clspart[g][0][n];
            a1 += g_clspart[g][1][n];
        }
        sinst[n]      = a0 * (1.0f / 96.0f) * 2.0f;
        sinst[NN + n] = a1 * (1.0f / 96.0f) * 2.0f;
    }
    if (tid < 768) {
        s1[tid]       = (&g_regpart[0][0][0][0])[tid];
        s1[768 + tid] = (&g_ioupart[0][0][0][0])[tid];
    }
    __syncthreads();
    if (tid < 2 * LL) {
        int br = tid >> 2, l = tid & 3;
        float rs = 0.0f, is = 0.0f;
        int base = br * 384 + l;
        #pragma unroll 8
        for (int sb = 0; sb < SS * BB; sb++) {
            rs += s1[base + sb * 4];
            is += s1[768 + base + sb * 4];
        }
        rs *= (1.0f / 96.0f);
        is *= (1.0f / 96.0f);
        int row = g_rows[br][SS - 1][BB - 1][l];
        sinst[br * NN + row] += rs * 0.5f + is * 2.0f;  // REG_W, IOU_W
    }
    __syncthreads();

    for (int n = tid; n < NN; n += 1024) {
        float x = sinst[n] - sinst[NN + n];
        unsigned u = __float_as_uint(x);
        su[n] = (u & 0x80000000u) ? ~u : (u | 0x80000000u);
    }
    __syncthreads();

    // dual-rank radix select (ranks 999 & 1000 in one sweep, 4 levels)
    {
        int k0 = 999, k1 = 1000;
        unsigned pf0 = 0, pf1 = 0;
        for (int shift = 24; shift >= 0; shift -= 8) {
            unsigned mask = (shift == 24) ? 0u : (0xFFFFFFFFu << (shift + 8));
            bool eq = (pf0 == pf1);
            if (tid < 512) hist[tid] = 0;
            __syncthreads();
            #pragma unroll
            for (int it = 0; it < 2; it++) {
                int i = tid + it * 1024;
                unsigned u = (i < NN) ? su[i] : 0u;
                bool act = (i < NN);
                unsigned m = u & mask;
                int d = (int)((u >> shift) & 255);
                int bin0 = (act && m == pf0) ? d : 512;
                unsigned mm0 = __match_any_sync(0xffffffffu, bin0);
                if (bin0 < 512 && lane == (__ffs(mm0) - 1))
                    atomicAdd(&hist[bin0], __popc(mm0));
                if (!eq) {
                    int bin1 = (act && m == pf1) ? 256 + d : 512;
                    unsigned mm1 = __match_any_sync(0xffffffffu, bin1);
                    if (bin1 < 512 && lane == (__ffs(mm1) - 1))
                        atomicAdd(&hist[bin1], __popc(mm1));
                }
            }
            __syncthreads();
            if (tid < 32) {
                int base = tid * 8, ssum = 0;
                int c[8];
                #pragma unroll
                for (int jj = 0; jj < 8; jj++) { c[jj] = hist[base + jj]; ssum += c[jj]; }
                int run = ssum;
                #pragma unroll
                for (int o = 1; o < 32; o <<= 1) {
                    int v = __shfl_up_sync(0xffffffffu, run, o);
                    if (lane >= o) run += v;
                }
                int excl = run - ssum;
                if (k0 >= excl && k0 < run) {
                    int a2 = excl;
                    #pragma unroll
                    for (int jj = 0; jj < 8; jj++) {
                        if (k0 < a2 + c[jj]) { s_d0 = base + jj; s_k0 = k0 - a2; break; }
                        a2 += c[jj];
                    }
                }
                if (eq && k1 >= excl && k1 < run) {
                    int a2 = excl;
                    #pragma unroll
                    for (int jj = 0; jj < 8; jj++) {
                        if (k1 < a2 + c[jj]) { s_d1 = base + jj; s_k1 = k1 - a2; break; }
                        a2 += c[jj];
                    }
                }
            } else if (tid >= 32 && tid < 64 && !eq) {
                int l2 = tid - 32;
                int base = 256 + l2 * 8, ssum = 0;
                int c[8];
                #pragma unroll
                for (int jj = 0; jj < 8; jj++) { c[jj] = hist[base + jj]; ssum += c[jj]; }
                int run = ssum;
                #pragma unroll
                for (int o = 1; o < 32; o <<= 1) {
                    int v = __shfl_up_sync(0xffffffffu, run, o);
                    if (l2 >= o) run += v;
                }
                int excl = run - ssum;
                if (k1 >= excl && k1 < run) {
                    int a2 = excl;
                    #pragma unroll
                    for (int jj = 0; jj < 8; jj++) {
                        if (k1 < a2 + c[jj]) { s_d1 = base - 256 + jj; s_k1 = k1 - a2; break; }
                        a2 += c[jj];
                    }
                }
            }
            __syncthreads();
            pf0 |= ((unsigned)s_d0) << shift;  k0 = s_k0;
            pf1 |= ((unsigned)s_d1) << shift;  k1 = s_k1;
        }
        if (tid == 0) {
            unsigned u0 = pf0, u1 = pf1;
            s_med[0] = (u0 & 0x80000000u) ? __uint_as_float(u0 ^ 0x80000000u)
                                          : __uint_as_float(~u0);
            s_med[1] = (u1 & 0x80000000u) ? __uint_as_float(u1 ^ 0x80000000u)
                                          : __uint_as_float(~u1);
        }
        __syncthreads();
    }
    float delta = 0.5f * (s_med[0] + s_med[1]);

    float acc = 0.0f;
    for (int n = tid; n < NN; n += 1024) {
        float dm = (diff[n] + diff[NN + n] + diff[2 * NN + n]) * (1.0f / 3.0f);
        acc += (1.0f - dm) * (sinst[n] - 0.5f * delta)
             + dm * (sinst[NN + n] + 0.5f * delta);
    }
    sred[tid] = acc;
    __syncthreads();
    for (int o = 512; o; o >>= 1) {
        if (tid < o) sred[tid] += sred[tid + o];
        __syncthreads();
    }
    if (tid == 0) out[0] = sred[0];
}

// ---------------------------------------------------------------------------
extern "C" void kernel_launch(void* const* d_in, const int* in_sizes, int n_in,
                              void* d_out, int out_size) {
    const float* pA   = (const float*)d_in[0];  // predictions_fir [S,B,N,D]
    const float* pB   = (const float*)d_in[1];  // predictions_sec [S,B,N,D]
    const float* gt   = (const float*)d_in[2];  // gt_lane [B,L,D]
    const float* diff = (const float*)d_in[3];  // diff [S,N]
    float* out = (float*)d_out;

    k_cost<<<NSLICE * NCHK, 320>>>(pA, pB, gt);      // 4800 blocks, assign inline
    k_rest<<<NBLK2, 1024>>>(pA, pB, gt, diff, out);  // cls+matched+finalize
}

// round 12
// speedup vs baseline: 1.1660x; 1.0410x over previous
#include <cuda_runtime.h>
#include <math.h>

// Problem constants
#define SS 3       // REFINE_LAYERS
#define BB 32      // batch
#define NN 2000    // priors
#define LL 4       // max lanes
#define DD 78      // 2 + 4 + 72
#define NP 72      // num points offsets
#define PRI 80     // priors per k_cost block
#define NCHK (NN / PRI)        // 25 chunk-blocks per slice
#define NSLICE (2 * SS * BB)   // 192
#define CLSG 8     // sb-groups for cls partials
#define SBPG (SS * BB / CLSG)  // 12 sb per group
#define NBLK2 56   // blocks in kernel 2 (32 cls + 24 matched)

// Scratch (device globals; no allocation allowed)
__device__ float2   g_clslog[2][SS][BB][NN];
__device__ float4   g_candv[NSLICE][LL][NCHK];  // per-chunk top-4 cost values
__device__ int4     g_candi[NSLICE][LL][NCHK];  // per-chunk top-4 prior indices
__device__ int      g_rows[2][SS][BB][LL];
__device__ float    g_clspart[CLSG][2][NN];     // cls partial sums (fixed slots)
__device__ float    g_regpart[2][SS][BB][LL];   // 768 floats
__device__ float    g_ioupart[2][SS][BB][LL];   // 768 floats
__device__ unsigned g_slice_cnt[NSLICE];        // monotonic (mod 25)
__device__ unsigned g_done;                     // monotonic (mod 56)

// ---------------------------------------------------------------------------
// Kernel 1: cost + log-softmax. pr = tid%80, l = tid/80 (warp = 32 consecutive
// priors, fixed l). Costs go to SHARED only; 4 warps then extract each
// column's top-4 (value,index)-lexicographic candidates -> tiny global write.
// Greedy needs at most 4 exclusions, so chosen rows are provably within the
// per-column global top-4 = subset of union of per-chunk top-4s (bit-exact).
// Last chunk-block of each slice runs the candidate-merge greedy inline.
// ---------------------------------------------------------------------------
__global__ void __launch_bounds__(320, 5) k_cost(const float* __restrict__ pA,
                                                 const float* __restrict__ pB,
                                                 const float* __restrict__ gt) {
    __shared__ float sp[PRI][84];    // prediction rows, dims at [2..79]
    __shared__ float sq[LL][NP];     // gt offsets * (1/799)
    __shared__ float sraw[LL][4];    // raw gt dims 2..5
    __shared__ float scost[LL][PRI]; // this chunk's cost columns
    __shared__ int   s_win;
    const int tid = threadIdx.x;

    const int chunk = blockIdx.x % NCHK;
    const int slice = blockIdx.x / NCHK;     // (br,s,b) id
    int t = slice;
    const int b = t % BB;  t /= BB;
    const int s = t % SS;  const int br = t / SS;
    const int n0 = chunk * PRI;

    // gt staging (312 values)
    for (int i = tid; i < LL * DD; i += 320) {
        int l = i / DD, d = i % DD;
        float v = gt[b * LL * DD + i];
        if (d >= 6)      sq[l][d - 6]   = v * (1.0f / 799.0f);
        else if (d >= 2) sraw[l][d - 2] = v;
    }
    // prediction staging: 80 rows x 39 float2; incremental row/col stepping
    const float2* p2 = (const float2*)((br ? pB : pA)
                     + ((size_t)((s * BB + b) * NN + n0)) * DD);
    {
        int r = tid / 39;
        int c = tid - r * 39;
        #pragma unroll
        for (int it = 0; it < 10; it++) {     // 3120 float2 over 320 threads
            int i = tid + it * 320;
            if (i < PRI * DD / 2) {
                float2 v = p2[i];
                *(float2*)&sp[r][2 + 2 * c] = v;
            }
            c += 8; r += 8;                   // 320 = 8*39 + 8
            if (c >= 39) { c -= 39; r += 1; }
        }
    }
    __syncthreads();

    {
        int pr = tid % PRI, l = tid / PRI;    // warp = 32 consecutive priors, fixed l
        float p0 = sp[pr][2], p1 = sp[pr][3];
        float mx  = fmaxf(p0, p1);
        float e0  = __expf(p0 - mx), e1 = __expf(p1 - mx);
        float sum = e0 + e1;
        float lse = mx + __logf(sum);
        float score = __fdividef(e1, sum);

        float4 g4 = *(const float4*)&sp[pr][4];    // dims 2..5
        float4 t4 = *(const float4*)&sraw[l][0];
        float geo = fabsf(g4.x - t4.x) + fabsf(g4.y - t4.y)
                  + fabsf(g4.z - t4.z) + fabsf(g4.w - t4.w);

        float off = 0.0f;
        #pragma unroll
        for (int k = 0; k < NP / 4; k++) {
            float4 a = *(const float4*)&sp[pr][8 + 4 * k];
            float4 q = *(const float4*)&sq[l][4 * k];
            off += fabsf(a.x - q.x) + fabsf(a.y - q.y)
                 + fabsf(a.z - q.z) + fabsf(a.w - q.w);
        }
        scost[l][pr] = geo + off * (1.0f / 72.0f) - score;
        if (l == 0)
            g_clslog[br][s][b][n0 + pr] = make_float2(p0 - lse, p1 - lse);  // coalesced
    }
    __syncthreads();

    // warps 0-3: per-column top-4 by (value, index) lexicographic
    const int wib = tid >> 5, lane = tid & 31;
    if (wib < LL) {
        int l = wib;
        float v0 = scost[l][lane];
        float v1 = scost[l][lane + 32];
        float v2 = (lane < 16) ? scost[l][lane + 64] : INFINITY;
        int i0 = n0 + lane, i1 = n0 + lane + 32;
        int i2 = (lane < 16) ? (n0 + lane + 64) : 0x7fffffff;

        float wv[4]; int wi[4];
        #pragma unroll
        for (int j = 0; j < 4; j++) {
            float lv = v0; int li = i0;
            if (v1 < lv || (v1 == lv && i1 < li)) { lv = v1; li = i1; }
            if (v2 < lv || (v2 == lv && i2 < li)) { lv = v2; li = i2; }
            #pragma unroll
            for (int o = 16; o; o >>= 1) {
                float ov = __shfl_xor_sync(0xffffffffu, lv, o);
                int   oi = __shfl_xor_sync(0xffffffffu, li, o);
                if (ov < lv || (ov == lv && oi < li)) { lv = ov; li = oi; }
            }
            wv[j] = lv; wi[j] = li;
            if (i0 == li) v0 = INFINITY;
            if (i1 == li) v1 = INFINITY;
            if (i2 == li) v2 = INFINITY;
        }
        if (lane == 0) {
            g_candv[slice][l][chunk] = make_float4(wv[0], wv[1], wv[2], wv[3]);
            g_candi[slice][l][chunk] = make_int4(wi[0], wi[1], wi[2], wi[3]);
        }
    }

    // ---- per-slice gate: last chunk-block merges candidates (greedy) ----
    __syncthreads();
    if (tid == 0) {
        __threadfence();
        unsigned old = atomicAdd(&g_slice_cnt[slice], 1u);
        s_win = ((old % NCHK) == NCHK - 1);
        if (s_win) __threadfence();
    }
    __syncthreads();
    if (!s_win) return;

    if (tid < 32) {
        int ch0 = -1, ch1 = -1, ch2 = -1;
        #pragma unroll
        for (int l = 0; l < LL; l++) {
            float4 v4; int4 i4;
            if (lane < NCHK) {
                v4 = g_candv[slice][l][lane];
                i4 = g_candi[slice][l][lane];
            } else {
                v4 = make_float4(INFINITY, INFINITY, INFINITY, INFINITY);
                i4 = make_int4(0x7fffffff, 0x7fffffff, 0x7fffffff, 0x7fffffff);
            }
            float lv = INFINITY; int li = 0x7fffffff;
            {
                float vv[4] = {v4.x, v4.y, v4.z, v4.w};
                int   ii[4] = {i4.x, i4.y, i4.z, i4.w};
                #pragma unroll
                for (int j = 0; j < 4; j++) {
                    bool excl = (ii[j] == ch0) | (ii[j] == ch1) | (ii[j] == ch2);
                    if (!excl && (vv[j] < lv || (vv[j] == lv && ii[j] < li))) {
                        lv = vv[j]; li = ii[j];
                    }
                }
            }
            #pragma unroll
            for (int o = 16; o; o >>= 1) {
                float ov = __shfl_xor_sync(0xffffffffu, lv, o);
                int   oi = __shfl_xor_sync(0xffffffffu, li, o);
                if (ov < lv || (ov == lv && oi < li)) { lv = ov; li = oi; }
            }
            if (l == 0) ch0 = li;
            else if (l == 1) ch1 = li;
            else if (l == 2) ch2 = li;
            if (lane == 0) g_rows[br][s][b][l] = li;
        }
    }
}

// ---------------------------------------------------------------------------
// Kernel 2 (round-8/11, unchanged): blocks 0-31 = focal cls partials
// (2 br x 2 n-halves x 8 sb-groups); blocks 32-55 = matched partials
// (32 warps each); last block (monotonic gate) runs finalize.
// ---------------------------------------------------------------------------
__global__ void __launch_bounds__(1024) k_rest(const float* __restrict__ pA,
                                               const float* __restrict__ pB,
                                               const float* __restrict__ gt,
                                               const float* __restrict__ diff,
                                               float* __restrict__ out) {
    __shared__ int      srows[SS * BB * LL];   // 384 (cls staging)
    __shared__ float    sinst[2 * NN];         // 16 KB (finalize)
    __shared__ float    s1[1536];              // reg/iou partial staging
    __shared__ unsigned su[NN];                // radix keys
    __shared__ int      hist[512];             // dual-track histograms
    __shared__ int      s_d0, s_k0, s_d1, s_k1;
    __shared__ float    s_med[2];
    __shared__ float    sred[1024];
    __shared__ int      s_last;
    const int tid = threadIdx.x;
    const int lane = tid & 31;

    if (blockIdx.x < 32) {
        // ---- cls partials: id = (br, nhalf, g) ----
        int id = blockIdx.x;
        int g  = id & 7;           // sb-group
        int nh = (id >> 3) & 1;    // n half
        int br = id >> 4;          // branch
        int n  = nh * 1024 + tid;

        const int* rsrc = &g_rows[br][0][0][0];
        if (tid < SS * BB * LL) srows[tid] = rsrc[tid];
        __syncthreads();

        if (n < NN) {
            const float2* lpbase = &g_clslog[br][0][0][0];
            float acc = 0.0f;
            int sb0 = g * SBPG;
            #pragma unroll
            for (int i = 0; i < SBPG; i++) {
                int sb = sb0 + i;
                float2 lp = lpbase[sb * NN + n];
                const int* r = &srows[sb * 4];
                bool matched = (r[0] == n) | (r[1] == n) | (r[2] == n) | (r[3] == n);
                float logpt = matched ? lp.y : lp.x;
                float pt = __expf(logpt);
                float a = matched ? 0.9f : 0.1f;
                float om = 1.0f - pt;
                acc += -a * om * om * logpt;
            }
            g_clspart[g][br][n] = acc;
        }
    } else {
        // ---- matched part: 32 warps/block, one (br,s,b,l) each ----
        int wib = tid >> 5;
        int id = (blockIdx.x - 32) * 32 + wib;   // [0, 768)
        int l = id % LL; int t = id / LL;
        int b = t % BB;  t /= BB;
        int s = t % SS;  int br = t / SS;

        int r = g_rows[br][s][b][l];
        const float* pm = (br ? pB : pA) + ((size_t)((s * BB + b) * NN + r)) * DD;
        const float* tg = gt + (b * LL + l) * DD;

        float sl = 0.0f;
        if (lane < 4) {
            const float scv[4] = {71.0f, 799.0f, 180.0f, 71.0f};
            float d = pm[2 + lane] * scv[lane] - tg[2 + lane] * scv[lane];
            float ad = fabsf(d);
            sl = (ad < 1.0f) ? 0.5f * d * d : ad - 0.5f;
        }
        float ovr = 0.0f, uni = 0.0f;
        #pragma unroll
        for (int jj = 0; jj < 3; jj++) {
            int j = lane + jj * 32;
            if (j < NP) {
                float rp = pm[6 + j] * 799.0f;
                float rt = tg[6 + j];
                bool inv = (rt < 0.0f) || (rt >= 800.0f);
                float o = fminf(rp + 15.0f, rt + 15.0f) - fmaxf(rp - 15.0f, rt - 15.0f);
                float u = fmaxf(rp + 15.0f, rt + 15.0f) - fminf(rp - 15.0f, rt - 15.0f);
                if (!inv) { ovr += o; uni += u; }
            }
        }
        #pragma unroll
        for (int o = 16; o; o >>= 1) {
            sl  += __shfl_xor_sync(0xffffffffu, sl,  o);
            ovr += __shfl_xor_sync(0xffffffffu, ovr, o);
            uni += __shfl_xor_sync(0xffffffffu, uni, o);
        }
        if (lane == 0) {
            float iou = ovr / (uni + 1e-9f);
            g_regpart[br][s][b][l] = (sl * 0.25f) / (float)LL;
            g_ioupart[br][s][b][l] = (1.0f - iou) / (float)LL;
        }
    }

    // ---- last-block gate (monotonic counter, no reset needed) ----
    __syncthreads();
    if (tid == 0) {
        __threadfence();
        unsigned old = atomicAdd(&g_done, 1u);
        s_last = ((old % (unsigned)NBLK2) == NBLK2 - 1u);
        if (s_last) __threadfence();
    }
    __syncthreads();
    if (!s_last) return;

    // ================= finalize (1024 threads) ===============================
    for (int n = tid; n < NN; n += 1024) {
        float a0 = 0.0f, a1 = 0.0f;
        #pragma unroll
        for (int g = 0; g < CLSG; g++) {
            a0 += g_clspart[g][0][n];
            a1 += g_clspart[g][1][n];
        }
        sinst[n]      = a0 * (1.0f / 96.0f) * 2.0f;
        sinst[NN + n] = a1 * (1.0f / 96.0f) * 2.0f;
    }
    if (tid < 768) {
        s1[tid]       = (&g_regpart[0][0][0][0])[tid];
        s1[768 + tid] = (&g_ioupart[0][0][0][0])[tid];
    }
    __syncthreads();
    if (tid < 2 * LL) {
        int br = tid >> 2, l = tid & 3;
        float rs = 0.0f, is = 0.0f;
        int base = br * 384 + l;
        #pragma unroll 8
        for (int sb = 0; sb < SS * BB; sb++) {
            rs += s1[base + sb * 4];
            is += s1[768 + base + sb * 4];
        }
        rs *= (1.0f / 96.0f);
        is *= (1.0f / 96.0f);
        int row = g_rows[br][SS - 1][BB - 1][l];
        sinst[br * NN + row] += rs * 0.5f + is * 2.0f;  // REG_W, IOU_W
    }
    __syncthreads();

    for (int n = tid; n < NN; n += 1024) {
        float x = sinst[n] - sinst[NN + n];
        unsigned u = __float_as_uint(x);
        su[n] = (u & 0x80000000u) ? ~u : (u | 0x80000000u);
    }
    __syncthreads();

    // dual-rank radix select (ranks 999 & 1000 in one sweep, 4 levels)
    {
        int k0 = 999, k1 = 1000;
        unsigned pf0 = 0, pf1 = 0;
        for (int shift = 24; shift >= 0; shift -= 8) {
            unsigned mask = (shift == 24) ? 0u : (0xFFFFFFFFu << (shift + 8));
            bool eq = (pf0 == pf1);
            if (tid < 512) hist[tid] = 0;
            __syncthreads();
            #pragma unroll
            for (int it = 0; it < 2; it++) {
                int i = tid + it * 1024;
                unsigned u = (i < NN) ? su[i] : 0u;
                bool act = (i < NN);
                unsigned m = u & mask;
                int d = (int)((u >> shift) & 255);
                int bin0 = (act && m == pf0) ? d : 512;
                unsigned mm0 = __match_any_sync(0xffffffffu, bin0);
                if (bin0 < 512 && lane == (__ffs(mm0) - 1))
                    atomicAdd(&hist[bin0], __popc(mm0));
                if (!eq) {
                    int bin1 = (act && m == pf1) ? 256 + d : 512;
                    unsigned mm1 = __match_any_sync(0xffffffffu, bin1);
                    if (bin1 < 512 && lane == (__ffs(mm1) - 1))
                        atomicAdd(&hist[bin1], __popc(mm1));
                }
            }
            __syncthreads();
            if (tid < 32) {
                int base = tid * 8, ssum = 0;
                int c[8];
                #pragma unroll
                for (int jj = 0; jj < 8; jj++) { c[jj] = hist[base + jj]; ssum += c[jj]; }
                int run = ssum;
                #pragma unroll
                for (int o = 1; o < 32; o <<= 1) {
                    int v = __shfl_up_sync(0xffffffffu, run, o);
                    if (lane >= o) run += v;
                }
                int excl = run - ssum;
                if (k0 >= excl && k0 < run) {
                    int a2 = excl;
                    #pragma unroll
                    for (int jj = 0; jj < 8; jj++) {
                        if (k0 < a2 + c[jj]) { s_d0 = base + jj; s_k0 = k0 - a2; break; }
                        a2 += c[jj];
                    }
                }
                if (eq && k1 >= excl && k1 < run) {
                    int a2 = excl;
                    #pragma unroll
                    for (int jj = 0; jj < 8; jj++) {
                        if (k1 < a2 + c[jj]) { s_d1 = base + jj; s_k1 = k1 - a2; break; }
                        a2 += c[jj];
                    }
                }
            } else if (tid >= 32 && tid < 64 && !eq) {
                int l2 = tid - 32;
                int base = 256 + l2 * 8, ssum = 0;
                int c[8];
                #pragma unroll
                for (int jj = 0; jj < 8; jj++) { c[jj] = hist[base + jj]; ssum += c[jj]; }
                int run = ssum;
                #pragma unroll
                for (int o = 1; o < 32; o <<= 1) {
                    int v = __shfl_up_sync(0xffffffffu, run, o);
                    if (l2 >= o) run += v;
                }
                int excl = run - ssum;
                if (k1 >= excl && k1 < run) {
                    int a2 = excl;
                    #pragma unroll
                    for (int jj = 0; jj < 8; jj++) {
                        if (k1 < a2 + c[jj]) { s_d1 = base - 256 + jj; s_k1 = k1 - a2; break; }
                        a2 += c[jj];
                    }
                }
            }
            __syncthreads();
            pf0 |= ((unsigned)s_d0) << shift;  k0 = s_k0;
            pf1 |= ((unsigned)s_d1) << shift;  k1 = s_k1;
        }
        if (tid == 0) {
            unsigned u0 = pf0, u1 = pf1;
            s_med[0] = (u0 & 0x80000000u) ? __uint_as_float(u0 ^ 0x80000000u)
                                          : __uint_as_float(~u0);
            s_med[1] = (u1 & 0x80000000u) ? __uint_as_float(u1 ^ 0x80000000u)
                                          : __uint_as_float(~u1);
        }
        __syncthreads();
    }
    float delta = 0.5f * (s_med[0] + s_med[1]);

    float acc = 0.0f;
    for (int n = tid; n < NN; n += 1024) {
        float dm = (diff[n] + diff[NN + n] + diff[2 * NN + n]) * (1.0f / 3.0f);
        acc += (1.0f - dm) * (sinst[n] - 0.5f * delta)
             + dm * (sinst[NN + n] + 0.5f * delta);
    }
    sred[tid] = acc;
    __syncthreads();
    for (int o = 512; o; o >>= 1) {
        if (tid < o) sred[tid] += sred[tid + o];
        __syncthreads();
    }
    if (tid == 0) out[0] = sred[0];
}

// ---------------------------------------------------------------------------
extern "C" void kernel_launch(void* const* d_in, const int* in_sizes, int n_in,
                              void* d_out, int out_size) {
    const float* pA   = (const float*)d_in[0];  // predictions_fir [S,B,N,D]
    const float* pB   = (const float*)d_in[1];  // predictions_sec [S,B,N,D]
    const float* gt   = (const float*)d_in[2];  // gt_lane [B,L,D]
    const float* diff = (const float*)d_in[3];  // diff [S,N]
    float* out = (float*)d_out;

    k_cost<<<NSLICE * NCHK, 320>>>(pA, pB, gt);      // 4800 blocks, candidates + greedy inline
    k_rest<<<NBLK2, 1024>>>(pA, pB, gt, diff, out);  // cls+matched+finalize
}

// round 13
// speedup vs baseline: 1.2563x; 1.0774x over previous
#include <cuda_runtime.h>
#include <math.h>

// Problem constants
#define SS 3       // REFINE_LAYERS
#define BB 32      // batch
#define NN 2000    // priors
#define LL 4       // max lanes
#define DD 78      // 2 + 4 + 72
#define NP 72      // num points offsets
#define PRI 80     // priors per k_cost block
#define NCHK (NN / PRI)        // 25 chunk-blocks per slice
#define NSLICE (2 * SS * BB)   // 192
#define CLSG 8     // sb-groups for cls partials
#define SBPG (SS * BB / CLSG)  // 12 sb per group
#define NBLK2 56   // blocks in kernel 2 (32 cls + 24 matched)

// Scratch (device globals; no allocation allowed)
__device__ float2   g_clslog[2][SS][BB][NN];
__device__ float4   g_candv[NSLICE][LL][NCHK];  // per-chunk top-4 cost values
__device__ int4     g_candi[NSLICE][LL][NCHK];  // per-chunk top-4 prior indices
__device__ int      g_rows[2][SS][BB][LL];
__device__ float    g_clspart[CLSG][2][NN];     // cls partial sums (fixed slots)
__device__ float    g_regpart[2][SS][BB][LL];   // 768 floats
__device__ float    g_ioupart[2][SS][BB][LL];   // 768 floats
__device__ unsigned g_slice_cnt[NSLICE];        // monotonic (mod 25)
__device__ unsigned g_done;                     // monotonic (mod 56)

// ---------------------------------------------------------------------------
// Kernel 1: cost + log-softmax, dim-split mapping pr = tid%80, qt = tid/80.
// Each thread loads its quarter of a prior's offset dims ONCE (no cross-warp
// p redundancy) and accumulates |p-q| against all 4 gt lanes (q loads are
// warp-broadcast = 1 crossbar phase). Quarter partials reduced via a tiny
// contiguous sacc round-trip; threads 0-79 assemble the 4 cost columns into
// shared. 4 warps extract per-column top-4 (value,index) candidates; the
// last chunk-block of each slice merges candidates with the greedy rule.
// ---------------------------------------------------------------------------
__global__ void __launch_bounds__(320, 5) k_cost(const float* __restrict__ pA,
                                                 const float* __restrict__ pB,
                                                 const float* __restrict__ gt) {
    __shared__ float  sp[PRI][84];    // prediction rows, dims at [2..79]
    __shared__ float  sq[LL][NP];     // gt offsets * (1/799)
    __shared__ float  sraw[LL][4];    // raw gt dims 2..5
    __shared__ float4 sacc[4][PRI];   // quarter partials: [qt][pr] = (a0..a3)
    __shared__ float  scost[LL][PRI]; // this chunk's cost columns
    __shared__ int    s_win;
    const int tid = threadIdx.x;

    const int chunk = blockIdx.x % NCHK;
    const int slice = blockIdx.x / NCHK;     // (br,s,b) id
    int t = slice;
    const int b = t % BB;  t /= BB;
    const int s = t % SS;  const int br = t / SS;
    const int n0 = chunk * PRI;

    // gt staging (312 values)
    for (int i = tid; i < LL * DD; i += 320) {
        int l = i / DD, d = i % DD;
        float v = gt[b * LL * DD + i];
        if (d >= 6)      sq[l][d - 6]   = v * (1.0f / 799.0f);
        else if (d >= 2) sraw[l][d - 2] = v;
    }
    // prediction staging: 80 rows x 39 float2; incremental row/col stepping
    const float2* p2 = (const float2*)((br ? pB : pA)
                     + ((size_t)((s * BB + b) * NN + n0)) * DD);
    {
        int r = tid / 39;
        int c = tid - r * 39;
        #pragma unroll
        for (int it = 0; it < 10; it++) {     // 3120 float2 over 320 threads
            int i = tid + it * 320;
            if (i < PRI * DD / 2) {
                float2 v = p2[i];
                *(float2*)&sp[r][2 + 2 * c] = v;
            }
            c += 8; r += 8;                   // 320 = 8*39 + 8
            if (c >= 39) { c -= 39; r += 1; }
        }
    }
    __syncthreads();

    // ---- phase 1: quarter accumulation (p read once, q broadcast) ----
    {
        const int pr = tid % PRI;
        const int qt = tid / PRI;                       // 0..3
        const int k0q  = (qt < 2) ? qt * 5 : 10 + (qt - 2) * 4;
        const int cntq = (qt < 2) ? 5 : 4;              // quarters 5,5,4,4
        float a0 = 0.f, a1 = 0.f, a2 = 0.f, a3 = 0.f;
        #pragma unroll
        for (int i = 0; i < 5; i++) {
            if (i < cntq) {
                int k = k0q + i;
                float4 p = *(const float4*)&sp[pr][8 + 4 * k];
                float4 q;
                q = *(const float4*)&sq[0][4 * k];
                a0 += fabsf(p.x - q.x) + fabsf(p.y - q.y)
                    + fabsf(p.z - q.z) + fabsf(p.w - q.w);
                q = *(const float4*)&sq[1][4 * k];
                a1 += fabsf(p.x - q.x) + fabsf(p.y - q.y)
                    + fabsf(p.z - q.z) + fabsf(p.w - q.w);
                q = *(const float4*)&sq[2][4 * k];
                a2 += fabsf(p.x - q.x) + fabsf(p.y - q.y)
                    + fabsf(p.z - q.z) + fabsf(p.w - q.w);
                q = *(const float4*)&sq[3][4 * k];
                a3 += fabsf(p.x - q.x) + fabsf(p.y - q.y)
                    + fabsf(p.z - q.z) + fabsf(p.w - q.w);
            }
        }
        sacc[qt][pr] = make_float4(a0, a1, a2, a3);
    }
    __syncthreads();

    // ---- phase 2: per-prior assembly (threads 0-79) ----
    if (tid < PRI) {
        const int pr = tid;
        float p0 = sp[pr][2], p1 = sp[pr][3];
        float mx  = fmaxf(p0, p1);
        float e0  = __expf(p0 - mx), e1 = __expf(p1 - mx);
        float sum = e0 + e1;
        float lse = mx + __logf(sum);
        float score = __fdividef(e1, sum);

        float4 s0 = sacc[0][pr], s1 = sacc[1][pr],
               s2 = sacc[2][pr], s3 = sacc[3][pr];
        float off0 = s0.x + s1.x + s2.x + s3.x;
        float off1 = s0.y + s1.y + s2.y + s3.y;
        float off2 = s0.z + s1.z + s2.z + s3.z;
        float off3 = s0.w + s1.w + s2.w + s3.w;

        float4 g4 = *(const float4*)&sp[pr][4];    // dims 2..5
        #pragma unroll
        for (int l = 0; l < LL; l++) {
            float4 t4 = *(const float4*)&sraw[l][0];
            float geo = fabsf(g4.x - t4.x) + fabsf(g4.y - t4.y)
                      + fabsf(g4.z - t4.z) + fabsf(g4.w - t4.w);
            float off = (l == 0) ? off0 : (l == 1) ? off1 : (l == 2) ? off2 : off3;
            scost[l][pr] = geo + off * (1.0f / 72.0f) - score;
        }
        g_clslog[br][s][b][n0 + pr] = make_float2(p0 - lse, p1 - lse);  // coalesced
    }
    __syncthreads();

    // warps 0-3: per-column top-4 by (value, index) lexicographic
    const int wib = tid >> 5, lane = tid & 31;
    if (wib < LL) {
        int l = wib;
        float v0 = scost[l][lane];
        float v1 = scost[l][lane + 32];
        float v2 = (lane < 16) ? scost[l][lane + 64] : INFINITY;
        int i0 = n0 + lane, i1 = n0 + lane + 32;
        int i2 = (lane < 16) ? (n0 + lane + 64) : 0x7fffffff;

        float wv[4]; int wi[4];
        #pragma unroll
        for (int j = 0; j < 4; j++) {
            float lv = v0; int li = i0;
            if (v1 < lv || (v1 == lv && i1 < li)) { lv = v1; li = i1; }
            if (v2 < lv || (v2 == lv && i2 < li)) { lv = v2; li = i2; }
            #pragma unroll
            for (int o = 16; o; o >>= 1) {
                float ov = __shfl_xor_sync(0xffffffffu, lv, o);
                int   oi = __shfl_xor_sync(0xffffffffu, li, o);
                if (ov < lv || (ov == lv && oi < li)) { lv = ov; li = oi; }
            }
            wv[j] = lv; wi[j] = li;
            if (i0 == li) v0 = INFINITY;
            if (i1 == li) v1 = INFINITY;
            if (i2 == li) v2 = INFINITY;
        }
        if (lane == 0) {
            g_candv[slice][l][chunk] = make_float4(wv[0], wv[1], wv[2], wv[3]);
            g_candi[slice][l][chunk] = make_int4(wi[0], wi[1], wi[2], wi[3]);
        }
    }

    // ---- per-slice gate: last chunk-block merges candidates (greedy) ----
    __syncthreads();
    if (tid == 0) {
        __threadfence();
        unsigned old = atomicAdd(&g_slice_cnt[slice], 1u);
        s_win = ((old % NCHK) == NCHK - 1);
        if (s_win) __threadfence();
    }
    __syncthreads();
    if (!s_win) return;

    if (tid < 32) {
        int ch0 = -1, ch1 = -1, ch2 = -1;
        #pragma unroll
        for (int l = 0; l < LL; l++) {
            float4 v4; int4 i4;
            if (lane < NCHK) {
                v4 = g_candv[slice][l][lane];
                i4 = g_candi[slice][l][lane];
            } else {
                v4 = make_float4(INFINITY, INFINITY, INFINITY, INFINITY);
                i4 = make_int4(0x7fffffff, 0x7fffffff, 0x7fffffff, 0x7fffffff);
            }
            float lv = INFINITY; int li = 0x7fffffff;
            {
                float vv[4] = {v4.x, v4.y, v4.z, v4.w};
                int   ii[4] = {i4.x, i4.y, i4.z, i4.w};
                #pragma unroll
                for (int j = 0; j < 4; j++) {
                    bool excl = (ii[j] == ch0) | (ii[j] == ch1) | (ii[j] == ch2);
                    if (!excl && (vv[j] < lv || (vv[j] == lv && ii[j] < li))) {
                        lv = vv[j]; li = ii[j];
                    }
                }
            }
            #pragma unroll
            for (int o = 16; o; o >>= 1) {
                float ov = __shfl_xor_sync(0xffffffffu, lv, o);
                int   oi = __shfl_xor_sync(0xffffffffu, li, o);
                if (ov < lv || (ov == lv && oi < li)) { lv = ov; li = oi; }
            }
            if (l == 0) ch0 = li;
            else if (l == 1) ch1 = li;
            else if (l == 2) ch2 = li;
            if (lane == 0) g_rows[br][s][b][l] = li;
        }
    }
}

// ---------------------------------------------------------------------------
// Kernel 2 (unchanged): blocks 0-31 = focal cls partials; blocks 32-55 =
// matched partials; last block (monotonic gate) runs finalize.
// ---------------------------------------------------------------------------
__global__ void __launch_bounds__(1024) k_rest(const float* __restrict__ pA,
                                               const float* __restrict__ pB,
                                               const float* __restrict__ gt,
                                               const float* __restrict__ diff,
                                               float* __restrict__ out) {
    __shared__ int      srows[SS * BB * LL];   // 384 (cls staging)
    __shared__ float    sinst[2 * NN];         // 16 KB (finalize)
    __shared__ float    s1[1536];              // reg/iou partial staging
    __shared__ unsigned su[NN];                // radix keys
    __shared__ int      hist[512];             // dual-track histograms
    __shared__ int      s_d0, s_k0, s_d1, s_k1;
    __shared__ float    s_med[2];
    __shared__ float    sred[1024];
    __shared__ int      s_last;
    const int tid = threadIdx.x;
    const int lane = tid & 31;

    if (blockIdx.x < 32) {
        // ---- cls partials: id = (br, nhalf, g) ----
        int id = blockIdx.x;
        int g  = id & 7;           // sb-group
        int nh = (id >> 3) & 1;    // n half
        int br = id >> 4;          // branch
        int n  = nh * 1024 + tid;

        const int* rsrc = &g_rows[br][0][0][0];
        if (tid < SS * BB * LL) srows[tid] = rsrc[tid];
        __syncthreads();

        if (n < NN) {
            const float2* lpbase = &g_clslog[br][0][0][0];
            float acc = 0.0f;
            int sb0 = g * SBPG;
            #pragma unroll
            for (int i = 0; i < SBPG; i++) {
                int sb = sb0 + i;
                float2 lp = lpbase[sb * NN + n];
                const int* r = &srows[sb * 4];
                bool matched = (r[0] == n) | (r[1] == n) | (r[2] == n) | (r[3] == n);
                float logpt = matched ? lp.y : lp.x;
                float pt = __expf(logpt);
                float a = matched ? 0.9f : 0.1f;
                float om = 1.0f - pt;
                acc += -a * om * om * logpt;
            }
            g_clspart[g][br][n] = acc;
        }
    } else {
        // ---- matched part: 32 warps/block, one (br,s,b,l) each ----
        int wib = tid >> 5;
        int id = (blockIdx.x - 32) * 32 + wib;   // [0, 768)
        int l = id % LL; int t = id / LL;
        int b = t % BB;  t /= BB;
        int s = t % SS;  int br = t / SS;

        int r = g_rows[br][s][b][l];
        const float* pm = (br ? pB : pA) + ((size_t)((s * BB + b) * NN + r)) * DD;
        const float* tg = gt + (b * LL + l) * DD;

        float sl = 0.0f;
        if (lane < 4) {
            const float scv[4] = {71.0f, 799.0f, 180.0f, 71.0f};
            float d = pm[2 + lane] * scv[lane] - tg[2 + lane] * scv[lane];
            float ad = fabsf(d);
            sl = (ad < 1.0f) ? 0.5f * d * d : ad - 0.5f;
        }
        float ovr = 0.0f, uni = 0.0f;
        #pragma unroll
        for (int jj = 0; jj < 3; jj++) {
            int j = lane + jj * 32;
            if (j < NP) {
                float rp = pm[6 + j] * 799.0f;
                float rt = tg[6 + j];
                bool inv = (rt < 0.0f) || (rt >= 800.0f);
                float o = fminf(rp + 15.0f, rt + 15.0f) - fmaxf(rp - 15.0f, rt - 15.0f);
                float u = fmaxf(rp + 15.0f, rt + 15.0f) - fminf(rp - 15.0f, rt - 15.0f);
                if (!inv) { ovr += o; uni += u; }
            }
        }
        #pragma unroll
        for (int o = 16; o; o >>= 1) {
            sl  += __shfl_xor_sync(0xffffffffu, sl,  o);
            ovr += __shfl_xor_sync(0xffffffffu, ovr, o);
            uni += __shfl_xor_sync(0xffffffffu, uni, o);
        }
        if (lane == 0) {
            float iou = ovr / (uni + 1e-9f);
            g_regpart[br][s][b][l] = (sl * 0.25f) / (float)LL;
            g_ioupart[br][s][b][l] = (1.0f - iou) / (float)LL;
        }
    }

    // ---- last-block gate (monotonic counter, no reset needed) ----
    __syncthreads();
    if (tid == 0) {
        __threadfence();
        unsigned old = atomicAdd(&g_done, 1u);
        s_last = ((old % (unsigned)NBLK2) == NBLK2 - 1u);
        if (s_last) __threadfence();
    }
    __syncthreads();
    if (!s_last) return;

    // ================= finalize (1024 threads) ===============================
    for (int n = tid; n < NN; n += 1024) {
        float a0 = 0.0f, a1 = 0.0f;
        #pragma unroll
        for (int g = 0; g < CLSG; g++) {
            a0 += g_clspart[g][0][n];
            a1 += g_clspart[g][1][n];
        }
        sinst[n]      = a0 * (1.0f / 96.0f) * 2.0f;
        sinst[NN + n] = a1 * (1.0f / 96.0f) * 2.0f;
    }
    if (tid < 768) {
        s1[tid]       = (&g_regpart[0][0][0][0])[tid];
        s1[768 + tid] = (&g_ioupart[0][0][0][0])[tid];
    }
    __syncthreads();
    if (tid < 2 * LL) {
        int br = tid >> 2, l = tid & 3;
        float rs = 0.0f, is = 0.0f;
        int base = br * 384 + l;
        #pragma unroll 8
        for (int sb = 0; sb < SS * BB; sb++) {
            rs += s1[base + sb * 4];
            is += s1[768 + base + sb * 4];
        }
        rs *= (1.0f / 96.0f);
        is *= (1.0f / 96.0f);
        int row = g_rows[br][SS - 1][BB - 1][l];
        sinst[br * NN + row] += rs * 0.5f + is * 2.0f;  // REG_W, IOU_W
    }
    __syncthreads();

    for (int n = tid; n < NN; n += 1024) {
        float x = sinst[n] - sinst[NN + n];
        unsigned u = __float_as_uint(x);
        su[n] = (u & 0x80000000u) ? ~u : (u | 0x80000000u);
    }
    __syncthreads();

    // dual-rank radix select (ranks 999 & 1000 in one sweep, 4 levels)
    {
        int k0 = 999, k1 = 1000;
        unsigned pf0 = 0, pf1 = 0;
        for (int shift = 24; shift >= 0; shift -= 8) {
            unsigned mask = (shift == 24) ? 0u : (0xFFFFFFFFu << (shift + 8));
            bool eq = (pf0 == pf1);
            if (tid < 512) hist[tid] = 0;
            __syncthreads();
            #pragma unroll
            for (int it = 0; it < 2; it++) {
                int i = tid + it * 1024;
                unsigned u = (i < NN) ? su[i] : 0u;
                bool act = (i < NN);
                unsigned m = u & mask;
                int d = (int)((u >> shift) & 255);
                int bin0 = (act && m == pf0) ? d : 512;
                unsigned mm0 = __match_any_sync(0xffffffffu, bin0);
                if (bin0 < 512 && lane == (__ffs(mm0) - 1))
                    atomicAdd(&hist[bin0], __popc(mm0));
                if (!eq) {
                    int bin1 = (act && m == pf1) ? 256 + d : 512;
                    unsigned mm1 = __match_any_sync(0xffffffffu, bin1);
                    if (bin1 < 512 && lane == (__ffs(mm1) - 1))
                        atomicAdd(&hist[bin1], __popc(mm1));
                }
            }
            __syncthreads();
            if (tid < 32) {
                int base = tid * 8, ssum = 0;
                int c[8];
                #pragma unroll
                for (int jj = 0; jj < 8; jj++) { c[jj] = hist[base + jj]; ssum += c[jj]; }
                int run = ssum;
                #pragma unroll
                for (int o = 1; o < 32; o <<= 1) {
                    int v = __shfl_up_sync(0xffffffffu, run, o);
                    if (lane >= o) run += v;
                }
                int excl = run - ssum;
                if (k0 >= excl && k0 < run) {
                    int a2 = excl;
                    #pragma unroll
                    for (int jj = 0; jj < 8; jj++) {
                        if (k0 < a2 + c[jj]) { s_d0 = base + jj; s_k0 = k0 - a2; break; }
                        a2 += c[jj];
                    }
                }
                if (eq && k1 >= excl && k1 < run) {
                    int a2 = excl;
                    #pragma unroll
                    for (int jj = 0; jj < 8; jj++) {
                        if (k1 < a2 + c[jj]) { s_d1 = base + jj; s_k1 = k1 - a2; break; }
                        a2 += c[jj];
                    }
                }
            } else if (tid >= 32 && tid < 64 && !eq) {
                int l2 = tid - 32;
                int base = 256 + l2 * 8, ssum = 0;
                int c[8];
                #pragma unroll
                for (int jj = 0; jj < 8; jj++) { c[jj] = hist[base + jj]; ssum += c[jj]; }
                int run = ssum;
                #pragma unroll
                for (int o = 1; o < 32; o <<= 1) {
                    int v = __shfl_up_sync(0xffffffffu, run, o);
                    if (l2 >= o) run += v;
                }
                int excl = run - ssum;
                if (k1 >= excl && k1 < run) {
                    int a2 = excl;
                    #pragma unroll
                    for (int jj = 0; jj < 8; jj++) {
                        if (k1 < a2 + c[jj]) { s_d1 = base - 256 + jj; s_k1 = k1 - a2; break; }
                        a2 += c[jj];
                    }
                }
            }
            __syncthreads();
            pf0 |= ((unsigned)s_d0) << shift;  k0 = s_k0;
            pf1 |= ((unsigned)s_d1) << shift;  k1 = s_k1;
        }
        if (tid == 0) {
            unsigned u0 = pf0, u1 = pf1;
            s_med[0] = (u0 & 0x80000000u) ? __uint_as_float(u0 ^ 0x80000000u)
                                          : __uint_as_float(~u0);
            s_med[1] = (u1 & 0x80000000u) ? __uint_as_float(u1 ^ 0x80000000u)
                                          : __uint_as_float(~u1);
        }
        __syncthreads();
    }
    float delta = 0.5f * (s_med[0] + s_med[1]);

    float acc = 0.0f;
    for (int n = tid; n < NN; n += 1024) {
        float dm = (diff[n] + diff[NN + n] + diff[2 * NN + n]) * (1.0f / 3.0f);
        acc += (1.0f - dm) * (sinst[n] - 0.5f * delta)
             + dm * (sinst[NN + n] + 0.5f * delta);
    }
    sred[tid] = acc;
    __syncthreads();
    for (int o = 512; o; o >>= 1) {
        if (tid < o) sred[tid] += sred[tid + o];
        __syncthreads();
    }
    if (tid == 0) out[0] = sred[0];
}

// ---------------------------------------------------------------------------
extern "C" void kernel_launch(void* const* d_in, const int* in_sizes, int n_in,
                              void* d_out, int out_size) {
    const float* pA   = (const float*)d_in[0];  // predictions_fir [S,B,N,D]
    const float* pB   = (const float*)d_in[1];  // predictions_sec [S,B,N,D]
    const float* gt   = (const float*)d_in[2];  // gt_lane [B,L,D]
    const float* diff = (const float*)d_in[3];  // diff [S,N]
    float* out = (float*)d_out;

    k_cost<<<NSLICE * NCHK, 320>>>(pA, pB, gt);      // 4800 blocks, candidates + greedy inline
    k_rest<<<NBLK2, 1024>>>(pA, pB, gt, diff, out);  // cls+matched+finalize
}